// round 9
// baseline (speedup 1.0000x reference)
#include <cuda_runtime.h>
#include <cuda_bf16.h>

// out[b] = sum_k x[b,k] * |W[k]| * fc1_w[k] + fc1_b
// B=32, K = T*P = 4,000,000
#define NBATCH  32
#define TP      4000000
#define NVEC    (TP / 4)      // 1,000,000 float4 per batch row
#define GROUPS  18            // column groups (proven shape)
#define THREADS 256
#define NBLOCKS (NBATCH * GROUPS)    // 576
#define STRIDE  (GROUPS * THREADS)   // 4608 float4 per sweep

// Zero-at-exit scratch: zero at module load; finalizer restores zero each run
// via L2 (.cg) stores -> deterministic across graph replays. No allocations.
__device__ float    g_partial[NBATCH];
__device__ unsigned g_count;

__global__ __launch_bounds__(THREADS, 4)
void dot_kernel(const float4* __restrict__ x,
                const float4* __restrict__ W,
                const float4* __restrict__ F,
                const float*  __restrict__ fc1_b,
                float* __restrict__ out) {
    const int b   = blockIdx.x & (NBATCH - 1);   // batch (fastest-varying)
    const int g   = blockIdx.x >> 5;             // column group 0..17
    const int tid = threadIdx.x;

    const float4* __restrict__ xb = x + (size_t)b * NVEC;

    float a0 = 0.f, a1 = 0.f, a2 = 0.f, a3 = 0.f;

#pragma unroll 4
    for (int j = g * THREADS + tid; j < NVEC; j += STRIDE) {
        // x: read-once stream -> evict-first so it can't thrash W/F in L2
        float4 xv = __ldcs(&xb[j]);
        // W/F: shared across the 32 co-resident batch-blocks -> L2 hits
        float4 w = __ldg(&W[j]);
        float4 f = __ldg(&F[j]);
        a0 = fmaf(xv.x, fabsf(w.x) * f.x, a0);
        a1 = fmaf(xv.y, fabsf(w.y) * f.y, a1);
        a2 = fmaf(xv.z, fabsf(w.z) * f.z, a2);
        a3 = fmaf(xv.w, fabsf(w.w) * f.w, a3);
    }

    float v = (a0 + a1) + (a2 + a3);

    // ---- block reduction: warp shfl -> smem -> one atomic per block ----
    __shared__ float sred[THREADS / 32];
    const int lane = tid & 31;
    const int wrp  = tid >> 5;

#pragma unroll
    for (int off = 16; off; off >>= 1)
        v += __shfl_xor_sync(0xffffffffu, v, off);
    if (lane == 0) sred[wrp] = v;
    __syncthreads();

    if (tid == 0) {
        float s = 0.f;
#pragma unroll
        for (int w2 = 0; w2 < THREADS / 32; w2++) s += sred[w2];
        // Partial accumulate at L2 (atomics never touch L1).
        atomicAdd(&g_partial[b], s);

        // Counter with acq_rel: release orders this thread's partial-add
        // before the increment; acquire covers the finalizer's L2 reads.
        // No fence instruction -> no CCTL.IVALL L1 flush (the R6 +9us bug).
        unsigned t;
        asm volatile("atom.acq_rel.gpu.global.add.u32 %0, [%1], %2;"
                     : "=r"(t) : "l"(&g_count), "r"(1u) : "memory");

        if (t == NBLOCKS - 1) {
            // Last block finalizes. All reads/writes of scratch via L2 (.cg),
            // so L1 staleness is impossible without any flush.
            float bias = fc1_b[0];
#pragma unroll
            for (int i = 0; i < NBATCH; i++) {
                float p;
                asm volatile("ld.global.cg.f32 %0, [%1];"
                             : "=f"(p) : "l"(&g_partial[i]) : "memory");
                out[i] = p + bias;
                asm volatile("st.global.cg.f32 [%0], %1;"
                             :: "l"(&g_partial[i]), "f"(0.0f) : "memory");
            }
            asm volatile("st.global.cg.u32 [%0], %1;"
                         :: "l"(&g_count), "r"(0u) : "memory");
        }
    }
}

extern "C" void kernel_launch(void* const* d_in, const int* in_sizes, int n_in,
                              void* d_out, int out_size) {
    const float4* x  = (const float4*)d_in[0];  // [32, 4M]
    const float4* W  = (const float4*)d_in[1];  // [4M]
    const float4* F  = (const float4*)d_in[2];  // fc1_w [4M]
    const float*  bb = (const float*)d_in[3];   // fc1_b [1]
    float* out = (float*)d_out;                 // [32]

    (void)in_sizes; (void)n_in; (void)out_size;

    dot_kernel<<<NBLOCKS, THREADS>>>(x, W, F, bb, out);
}

// round 10
// speedup vs baseline: 1.1532x; 1.1532x over previous
#include <cuda_runtime.h>
#include <cuda_bf16.h>

// out[b] = sum_k x[b,k] * |W[k]| * fc1_w[k] + fc1_b
// B=32, K = T*P = 4,000,000
#define NBATCH  32
#define TP      4000000
#define NVEC    (TP / 4)      // 1,000,000 float4 per batch row
#define GROUPS  27            // column groups -> grid 864 ~= 148 SM * 6 CTA
#define THREADS 256
#define STRIDE  (GROUPS * THREADS)   // 6912 float4 per sweep

__global__ void init_out_kernel(const float* __restrict__ fc1_b,
                                float* __restrict__ out) {
    out[threadIdx.x] = fc1_b[0];
}

__global__ __launch_bounds__(THREADS, 6)   // cap regs at 42 -> 6 CTAs/SM
void dot_kernel(const float4* __restrict__ x,
                const float4* __restrict__ W,
                const float4* __restrict__ F,
                float* __restrict__ out) {
    const int b   = blockIdx.x & (NBATCH - 1);   // batch (fastest-varying)
    const int g   = blockIdx.x >> 5;             // column group 0..26
    const int tid = threadIdx.x;

    const float4* __restrict__ xb = x + (size_t)b * NVEC;

    float a0 = 0.f, a1 = 0.f, a2 = 0.f, a3 = 0.f;

    // unroll 2 (not 4): keeps live float4 count at 6 -> ~40 regs, no spills
#pragma unroll 2
    for (int j = g * THREADS + tid; j < NVEC; j += STRIDE) {
        // x: read-once stream -> evict-first so it can't thrash W/F in L2
        float4 xv = __ldcs(&xb[j]);
        // W/F: shared across the 32 co-resident batch-blocks -> L2 hits
        float4 w = __ldg(&W[j]);
        float4 f = __ldg(&F[j]);
        a0 = fmaf(xv.x, fabsf(w.x) * f.x, a0);
        a1 = fmaf(xv.y, fabsf(w.y) * f.y, a1);
        a2 = fmaf(xv.z, fabsf(w.z) * f.z, a2);
        a3 = fmaf(xv.w, fabsf(w.w) * f.w, a3);
    }

    float v = (a0 + a1) + (a2 + a3);

    // ---- block reduction: warp shfl -> smem -> single atomic ----
    __shared__ float sred[THREADS / 32];
    const int lane = tid & 31;
    const int wrp  = tid >> 5;

#pragma unroll
    for (int off = 16; off; off >>= 1)
        v += __shfl_xor_sync(0xffffffffu, v, off);
    if (lane == 0) sred[wrp] = v;
    __syncthreads();

    if (wrp == 0) {
        float s = (lane < THREADS / 32) ? sred[lane] : 0.f;
#pragma unroll
        for (int off = 4; off; off >>= 1)
            s += __shfl_xor_sync(0xffffffffu, s, off);
        if (lane == 0) atomicAdd(&out[b], s);
    }
}

extern "C" void kernel_launch(void* const* d_in, const int* in_sizes, int n_in,
                              void* d_out, int out_size) {
    const float4* x  = (const float4*)d_in[0];  // [32, 4M]
    const float4* W  = (const float4*)d_in[1];  // [4M]
    const float4* F  = (const float4*)d_in[2];  // fc1_w [4M]
    const float*  bb = (const float*)d_in[3];   // fc1_b [1]
    float* out = (float*)d_out;                 // [32]

    (void)in_sizes; (void)n_in; (void)out_size;

    init_out_kernel<<<1, NBATCH>>>(bb, out);
    dot_kernel<<<NBATCH * GROUPS, THREADS>>>(x, W, F, out);
}